// round 1
// baseline (speedup 1.0000x reference)
#include <cuda_runtime.h>
#include <math.h>

#define NN 100000
#define D1 128
#define D2 64

// ---------------- scratch (static __device__ — no runtime allocation) ----------------
__device__ float g_dis[NN];                         // deg -> rsqrt(deg)
__device__ float g_H1[(size_t)NN * D1];             // x @ W1
__device__ float g_A1[(size_t)NN * D1];             // aggregated layer-1 (pre-relu, pre-bias)
__device__ float g_H2[(size_t)NN * D2];             // relu(A1+b1) @ W2
__device__ float g_A2[(size_t)NN * D2];             // aggregated layer-2
__device__ int   g_is64;                            // edge_index dtype flag

// ---------------- helpers ----------------
__device__ __forceinline__ int load_idx(const void* ei, long long pos, int is64) {
    return is64 ? (int)((const long long*)ei)[pos] : ((const int*)ei)[pos];
}

__device__ __forceinline__ void red_add_v4(float* addr, float4 v) {
    asm volatile("red.global.add.v4.f32 [%0], {%1,%2,%3,%4};"
                 :: "l"(addr), "f"(v.x), "f"(v.y), "f"(v.z), "f"(v.w) : "memory");
}

// Detect whether edge_index is int64 or int32: for int64 nonneg values < 2^31,
// every high 32-bit word is zero. For int32 data the odd words are random
// node indices (overwhelmingly nonzero across 2048 samples).
__global__ void detect_kernel(const unsigned int* ei) {
    __shared__ int any;
    if (threadIdx.x == 0) any = 0;
    __syncthreads();
    int local = 0;
    for (int i = threadIdx.x; i < 2048; i += blockDim.x)
        if (ei[2 * i + 1] != 0u) local = 1;
    if (local) any = 1;
    __syncthreads();
    if (threadIdx.x == 0) g_is64 = (any == 0) ? 1 : 0;
}

__global__ void init_deg_kernel(int n) {
    int i = blockIdx.x * blockDim.x + threadIdx.x;
    if (i < n) g_dis[i] = 1.0f;   // self-loop
}

__global__ void count_kernel(const void* __restrict__ ei, long long E) {
    long long e = (long long)blockIdx.x * blockDim.x + threadIdx.x;
    if (e >= E) return;
    int is64 = g_is64;
    int dst = load_idx(ei, E + e, is64);
    atomicAdd(&g_dis[dst], 1.0f);
}

__global__ void rsqrt_kernel(int n) {
    int i = blockIdx.x * blockDim.x + threadIdx.x;
    if (i < n) g_dis[i] = rsqrtf(g_dis[i]);
}

// ---------------- GEMM: H = X@W ; A = H * dis[row]^2  (self-loop init) ----------------
// IN fixed at 128. OUT is 128 (CPL=4) or 64 (CPL=2).
// If RELU_IN: input row transform v = relu(v + bin) applied on load.
template <int OUT, bool RELU_IN>
__global__ void gemm_kernel(const float* __restrict__ X, const float* __restrict__ W,
                            const float* __restrict__ bin,
                            float* __restrict__ H, float* __restrict__ A, int n) {
    constexpr int IN = 128;
    constexpr int CPL = OUT / 32;   // cols per lane
    extern __shared__ float smem[];
    float* Ws = smem;                                    // IN*OUT
    float* xs = smem + IN * OUT + (threadIdx.x >> 5) * (4 * IN);  // per-warp 4-row stage
    const int lane = threadIdx.x & 31;

    for (int i = threadIdx.x; i < IN * OUT; i += blockDim.x) Ws[i] = W[i];
    __syncthreads();

    for (int it = 0; it < 4; ++it) {
        const int r0 = blockIdx.x * 128 + it * 32 + (threadIdx.x >> 5) * 4;
        if (r0 >= n) break;

        // stage 4 input rows (with optional relu+bias)
        #pragma unroll
        for (int j = 0; j < 4; ++j) {
            const int row = r0 + j;
            float4 v = make_float4(0.f, 0.f, 0.f, 0.f);
            if (row < n) {
                v = *(const float4*)&X[(size_t)row * IN + lane * 4];
                if (RELU_IN) {
                    const float4 b = *(const float4*)&bin[lane * 4];
                    v.x = fmaxf(v.x + b.x, 0.f);
                    v.y = fmaxf(v.y + b.y, 0.f);
                    v.z = fmaxf(v.z + b.z, 0.f);
                    v.w = fmaxf(v.w + b.w, 0.f);
                }
            }
            *(float4*)&xs[j * IN + lane * 4] = v;
        }
        __syncwarp();

        float acc[4][CPL];
        #pragma unroll
        for (int j = 0; j < 4; ++j)
            #pragma unroll
            for (int c = 0; c < CPL; ++c) acc[j][c] = 0.f;

        #pragma unroll 4
        for (int k = 0; k < IN; ++k) {
            float wv[CPL];
            if (CPL == 4) {
                const float4 w4 = *(const float4*)&Ws[k * OUT + lane * 4];
                wv[0] = w4.x; wv[1] = w4.y; wv[2] = w4.z; wv[3] = w4.w;
            } else {
                const float2 w2 = *(const float2*)&Ws[k * OUT + lane * 2];
                wv[0] = w2.x; wv[1] = w2.y;
            }
            #pragma unroll
            for (int j = 0; j < 4; ++j) {
                const float xv = xs[j * IN + k];
                #pragma unroll
                for (int c = 0; c < CPL; ++c) acc[j][c] = fmaf(xv, wv[c], acc[j][c]);
            }
        }
        __syncwarp();

        #pragma unroll
        for (int j = 0; j < 4; ++j) {
            const int row = r0 + j;
            if (row >= n) continue;
            float id = g_dis[row];
            id *= id;   // 1/deg
            if (CPL == 4) {
                float4 h = make_float4(acc[j][0], acc[j][1], acc[j][2], acc[j][3]);
                float4 a = make_float4(h.x * id, h.y * id, h.z * id, h.w * id);
                *(float4*)&H[(size_t)row * OUT + lane * 4] = h;
                *(float4*)&A[(size_t)row * OUT + lane * 4] = a;
            } else {
                float2 h = make_float2(acc[j][0], acc[j][1]);
                float2 a = make_float2(h.x * id, h.y * id);
                *(float2*)&H[(size_t)row * OUT + lane * 2] = h;
                *(float2*)&A[(size_t)row * OUT + lane * 2] = a;
            }
        }
    }
}

// ---------------- edge scatter: A[dst] += H[src] * dis[src]*dis[dst] ----------------
template <int D>
__global__ void scatter_kernel(const void* __restrict__ ei, long long E,
                               const float* __restrict__ H, float* __restrict__ A) {
    constexpr int LPE = D / 4;   // lanes per edge (32 for D=128, 16 for D=64)
    const long long gt = (long long)blockIdx.x * blockDim.x + threadIdx.x;
    const long long e = gt / LPE;
    const int l = (int)(gt % LPE);
    if (e >= E) return;
    const int is64 = g_is64;
    const int src = load_idx(ei, e, is64);
    const int dst = load_idx(ei, E + e, is64);
    const float nrm = g_dis[src] * g_dis[dst];
    float4 v = *(const float4*)&H[(size_t)src * D + l * 4];
    v.x *= nrm; v.y *= nrm; v.z *= nrm; v.w *= nrm;
    red_add_v4(&A[(size_t)dst * D + l * 4], v);
}

// ---------------- final: out = softmax(relu(A2+b2) @ Wf + bf) ----------------
__global__ void final_kernel(const float* __restrict__ A2, const float* __restrict__ b2,
                             const float* __restrict__ Wf, const float* __restrict__ bf,
                             float* __restrict__ out, int n) {
    __shared__ float Wfs[64 * 10];
    __shared__ float bfs[10];
    __shared__ float b2s[64];
    for (int i = threadIdx.x; i < 640; i += blockDim.x) Wfs[i] = Wf[i];
    if (threadIdx.x < 10) bfs[threadIdx.x] = bf[threadIdx.x];
    if (threadIdx.x < 64) b2s[threadIdx.x] = b2[threadIdx.x];
    __syncthreads();

    const int i = blockIdx.x * blockDim.x + threadIdx.x;
    if (i >= n) return;

    float acc[10];
    #pragma unroll
    for (int c = 0; c < 10; ++c) acc[c] = bfs[c];

    #pragma unroll
    for (int kk = 0; kk < 64; kk += 4) {
        float4 v = *(const float4*)&A2[(size_t)i * 64 + kk];
        v.x = fmaxf(v.x + b2s[kk + 0], 0.f);
        v.y = fmaxf(v.y + b2s[kk + 1], 0.f);
        v.z = fmaxf(v.z + b2s[kk + 2], 0.f);
        v.w = fmaxf(v.w + b2s[kk + 3], 0.f);
        #pragma unroll
        for (int c = 0; c < 10; ++c) {
            acc[c] = fmaf(v.x, Wfs[(kk + 0) * 10 + c], acc[c]);
            acc[c] = fmaf(v.y, Wfs[(kk + 1) * 10 + c], acc[c]);
            acc[c] = fmaf(v.z, Wfs[(kk + 2) * 10 + c], acc[c]);
            acc[c] = fmaf(v.w, Wfs[(kk + 3) * 10 + c], acc[c]);
        }
    }

    float m = acc[0];
    #pragma unroll
    for (int c = 1; c < 10; ++c) m = fmaxf(m, acc[c]);
    float s = 0.f;
    float ex[10];
    #pragma unroll
    for (int c = 0; c < 10; ++c) { ex[c] = expf(acc[c] - m); s += ex[c]; }
    const float inv = 1.0f / s;
    #pragma unroll
    for (int c = 0; c < 10; ++c) out[(size_t)i * 10 + c] = ex[c] * inv;
}

// ---------------- launch ----------------
extern "C" void kernel_launch(void* const* d_in, const int* in_sizes, int n_in,
                              void* d_out, int out_size) {
    const float* x  = (const float*)d_in[0];
    const void*  ei = d_in[1];
    const float* W1 = (const float*)d_in[2];
    const float* b1 = (const float*)d_in[3];
    const float* W2 = (const float*)d_in[4];
    const float* b2 = (const float*)d_in[5];
    const float* Wf = (const float*)d_in[6];
    const float* bf = (const float*)d_in[7];
    float* out = (float*)d_out;

    const long long E = (long long)in_sizes[1] / 2;
    const int n = in_sizes[0] / D1;

    float *H1, *A1, *H2, *A2;
    cudaGetSymbolAddress((void**)&H1, g_H1);
    cudaGetSymbolAddress((void**)&A1, g_A1);
    cudaGetSymbolAddress((void**)&H2, g_H2);
    cudaGetSymbolAddress((void**)&A2, g_A2);

    cudaFuncSetAttribute(gemm_kernel<128, false>,
                         cudaFuncAttributeMaxDynamicSharedMemorySize, 81920);
    cudaFuncSetAttribute(gemm_kernel<64, true>,
                         cudaFuncAttributeMaxDynamicSharedMemorySize, 49152);

    detect_kernel<<<1, 256>>>((const unsigned int*)ei);
    init_deg_kernel<<<(n + 255) / 256, 256>>>(n);
    if (E > 0) count_kernel<<<(int)((E + 255) / 256), 256>>>(ei, E);
    rsqrt_kernel<<<(n + 255) / 256, 256>>>(n);

    // layer 1
    gemm_kernel<128, false><<<(n + 127) / 128, 256, 81920>>>(x, W1, nullptr, H1, A1, n);
    if (E > 0) scatter_kernel<128><<<(int)((E * 32 + 255) / 256), 256>>>(ei, E, H1, A1);

    // layer 2 (relu(+b1) fused into input load)
    gemm_kernel<64, true><<<(n + 127) / 128, 256, 49152>>>(A1, W2, b1, H2, A2, n);
    if (E > 0) scatter_kernel<64><<<(int)((E * 16 + 255) / 256), 256>>>(ei, E, H2, A2);

    // final dense + softmax (relu(+b2) fused into load)
    final_kernel<<<(n + 255) / 256, 256>>>(A2, b2, Wf, bf, out, n);
}

// round 3
// speedup vs baseline: 1.5982x; 1.5982x over previous
#include <cuda_runtime.h>
#include <math.h>

#define NN 100000
#define D1 128
#define D2 64
#define EMAX 4000000
#define SCAN_BLK 1024
#define MAXNB 128

// ---------------- scratch (static __device__ — no runtime allocation) ----------------
__device__ float g_dis[NN];                         // rsqrt(deg+1)
__device__ int   g_deg[NN];                         // in-degree (real edges only)
__device__ int   g_rowstart[NN];                    // CSR row offsets (exclusive scan)
__device__ int   g_cursor[NN];                      // fill cursors
__device__ int   g_csr[EMAX];                       // CSR column (src) indices
__device__ int   g_blocksum[MAXNB];
__device__ int   g_blockoff[MAXNB];
__device__ float g_Hs1[(size_t)NN * D1];            // (x @ W1) * dis[row]
__device__ float g_A1[(size_t)NN * D1];             // aggregated layer-1
__device__ float g_Hs2[(size_t)NN * D2];            // (relu(A1+b1) @ W2) * dis[row]
__device__ float g_A2[(size_t)NN * D2];             // aggregated layer-2
__device__ int   g_is64;                            // edge_index dtype flag

// ---------------- helpers ----------------
__device__ __forceinline__ int load_idx(const void* ei, long long pos, int is64) {
    return is64 ? (int)((const long long*)ei)[pos] : ((const int*)ei)[pos];
}

// int64 vs int32 detection: for int64 nonneg < 2^31 the high words are all 0.
__global__ void detect_kernel(const unsigned int* ei) {
    __shared__ int any;
    if (threadIdx.x == 0) any = 0;
    __syncthreads();
    int local = 0;
    for (int i = threadIdx.x; i < 2048; i += blockDim.x)
        if (ei[2 * i + 1] != 0u) local = 1;
    if (local) any = 1;
    __syncthreads();
    if (threadIdx.x == 0) g_is64 = (any == 0) ? 1 : 0;
}

__global__ void zero_deg_kernel(int n) {
    int i = blockIdx.x * blockDim.x + threadIdx.x;
    if (i < n) g_deg[i] = 0;
}

__global__ void count_kernel(const void* __restrict__ ei, long long E) {
    long long e = (long long)blockIdx.x * blockDim.x + threadIdx.x;
    if (e >= E) return;
    int dst = load_idx(ei, E + e, g_is64);
    atomicAdd(&g_deg[dst], 1);
}

// ---- 2-level exclusive prefix scan over g_deg -> g_rowstart / g_cursor; also dis ----
__global__ void scanA_kernel(int n) {           // per-block sums
    __shared__ int s[SCAN_BLK];
    int i = blockIdx.x * SCAN_BLK + threadIdx.x;
    s[threadIdx.x] = (i < n) ? g_deg[i] : 0;
    __syncthreads();
    for (int off = SCAN_BLK / 2; off > 0; off >>= 1) {
        if (threadIdx.x < off) s[threadIdx.x] += s[threadIdx.x + off];
        __syncthreads();
    }
    if (threadIdx.x == 0) g_blocksum[blockIdx.x] = s[0];
}

__global__ void scanB_kernel(int nb) {          // scan block sums (1 block, 128 thr)
    __shared__ int s[MAXNB];
    int v = (threadIdx.x < nb) ? g_blocksum[threadIdx.x] : 0;
    s[threadIdx.x] = v;
    __syncthreads();
    for (int off = 1; off < MAXNB; off <<= 1) {
        int t = (threadIdx.x >= off) ? s[threadIdx.x - off] : 0;
        __syncthreads();
        s[threadIdx.x] += t;
        __syncthreads();
    }
    if (threadIdx.x < nb) g_blockoff[threadIdx.x] = s[threadIdx.x] - v;  // exclusive
}

__global__ void scanC_kernel(int n) {           // local scan + block offset
    __shared__ int s[SCAN_BLK];
    int i = blockIdx.x * SCAN_BLK + threadIdx.x;
    int v = (i < n) ? g_deg[i] : 0;
    s[threadIdx.x] = v;
    __syncthreads();
    for (int off = 1; off < SCAN_BLK; off <<= 1) {
        int t = (threadIdx.x >= off) ? s[threadIdx.x - off] : 0;
        __syncthreads();
        s[threadIdx.x] += t;
        __syncthreads();
    }
    if (i < n) {
        int excl = s[threadIdx.x] - v + g_blockoff[blockIdx.x];
        g_rowstart[i] = excl;
        g_cursor[i] = excl;
        g_dis[i] = rsqrtf((float)(v + 1));      // +1 self-loop
    }
}

__global__ void fill_kernel(const void* __restrict__ ei, long long E) {
    long long e = (long long)blockIdx.x * blockDim.x + threadIdx.x;
    if (e >= E) return;
    const int is64 = g_is64;
    int src = load_idx(ei, e, is64);
    int dst = load_idx(ei, E + e, is64);
    int pos = atomicAdd(&g_cursor[dst], 1);
    g_csr[pos] = src;
}

// ---------------- GEMM: Hs = (X@W) * dis[row]  (optionally relu(X+bin) on load) ----
template <int OUT, bool RELU_IN>
__global__ void gemm_kernel(const float* __restrict__ X, const float* __restrict__ W,
                            const float* __restrict__ bin,
                            float* __restrict__ Hs, int n) {
    constexpr int IN = 128;
    constexpr int CPL = OUT / 32;   // cols per lane
    extern __shared__ float smem[];
    float* Ws = smem;                                              // IN*OUT
    float* xs = smem + IN * OUT + (threadIdx.x >> 5) * (4 * IN);   // per-warp stage
    const int lane = threadIdx.x & 31;

    for (int i = threadIdx.x; i < IN * OUT; i += blockDim.x) Ws[i] = W[i];
    __syncthreads();

    for (int it = 0; it < 4; ++it) {
        const int r0 = blockIdx.x * 128 + it * 32 + (threadIdx.x >> 5) * 4;
        if (r0 >= n) break;

        #pragma unroll
        for (int j = 0; j < 4; ++j) {
            const int row = r0 + j;
            float4 v = make_float4(0.f, 0.f, 0.f, 0.f);
            if (row < n) {
                v = *(const float4*)&X[(size_t)row * IN + lane * 4];
                if (RELU_IN) {
                    const float4 b = *(const float4*)&bin[lane * 4];
                    v.x = fmaxf(v.x + b.x, 0.f);
                    v.y = fmaxf(v.y + b.y, 0.f);
                    v.z = fmaxf(v.z + b.z, 0.f);
                    v.w = fmaxf(v.w + b.w, 0.f);
                }
            }
            *(float4*)&xs[j * IN + lane * 4] = v;
        }
        __syncwarp();

        float acc[4][CPL];
        #pragma unroll
        for (int j = 0; j < 4; ++j)
            #pragma unroll
            for (int c = 0; c < CPL; ++c) acc[j][c] = 0.f;

        #pragma unroll 4
        for (int k = 0; k < IN; ++k) {
            float wv[CPL];
            if (CPL == 4) {
                const float4 w4 = *(const float4*)&Ws[k * OUT + lane * 4];
                wv[0] = w4.x; wv[1] = w4.y; wv[2] = w4.z; wv[3] = w4.w;
            } else {
                const float2 w2 = *(const float2*)&Ws[k * OUT + lane * 2];
                wv[0] = w2.x; wv[1] = w2.y;
            }
            #pragma unroll
            for (int j = 0; j < 4; ++j) {
                const float xv = xs[j * IN + k];
                #pragma unroll
                for (int c = 0; c < CPL; ++c) acc[j][c] = fmaf(xv, wv[c], acc[j][c]);
            }
        }
        __syncwarp();

        #pragma unroll
        for (int j = 0; j < 4; ++j) {
            const int row = r0 + j;
            if (row >= n) continue;
            const float d = g_dis[row];
            if (CPL == 4) {
                float4 h = make_float4(acc[j][0] * d, acc[j][1] * d,
                                       acc[j][2] * d, acc[j][3] * d);
                *(float4*)&Hs[(size_t)row * OUT + lane * 4] = h;
            } else {
                float2 h = make_float2(acc[j][0] * d, acc[j][1] * d);
                *(float2*)&Hs[(size_t)row * OUT + lane * 2] = h;
            }
        }
    }
}

// ---------------- gather: A[dst] = dis[dst] * (Hs[dst] + sum_{src in N(dst)} Hs[src]) ----
template <int D>
__global__ void gather_kernel(const float* __restrict__ Hs, float* __restrict__ A, int n) {
    constexpr int LPN = D / 4;   // lanes per node
    const long long gt = (long long)blockIdx.x * blockDim.x + threadIdx.x;
    const int node = (int)(gt / LPN);
    const int l = (int)(gt % LPN);
    if (node >= n) return;

    const float4* __restrict__ hs4 = (const float4*)Hs;
    const size_t col = (size_t)node * LPN + l;

    float4 acc = hs4[col];   // self term
    const int beg = g_rowstart[node];
    const int cnt = g_deg[node];

    #pragma unroll 4
    for (int j = 0; j < cnt; ++j) {
        const int src = __ldg(&g_csr[beg + j]);
        const float4 v = hs4[(size_t)src * LPN + l];
        acc.x += v.x; acc.y += v.y; acc.z += v.z; acc.w += v.w;
    }

    const float d = g_dis[node];
    float4 o = make_float4(acc.x * d, acc.y * d, acc.z * d, acc.w * d);
    ((float4*)A)[col] = o;
}

// ---------------- final: out = softmax(relu(A2+b2) @ Wf + bf) ----------------
__global__ void final_kernel(const float* __restrict__ A2, const float* __restrict__ b2,
                             const float* __restrict__ Wf, const float* __restrict__ bf,
                             float* __restrict__ out, int n) {
    __shared__ float Wfs[64 * 10];
    __shared__ float bfs[10];
    __shared__ float b2s[64];
    for (int i = threadIdx.x; i < 640; i += blockDim.x) Wfs[i] = Wf[i];
    if (threadIdx.x < 10) bfs[threadIdx.x] = bf[threadIdx.x];
    if (threadIdx.x < 64) b2s[threadIdx.x] = b2[threadIdx.x];
    __syncthreads();

    const int i = blockIdx.x * blockDim.x + threadIdx.x;
    if (i >= n) return;

    float acc[10];
    #pragma unroll
    for (int c = 0; c < 10; ++c) acc[c] = bfs[c];

    #pragma unroll
    for (int kk = 0; kk < 64; kk += 4) {
        float4 v = *(const float4*)&A2[(size_t)i * 64 + kk];
        v.x = fmaxf(v.x + b2s[kk + 0], 0.f);
        v.y = fmaxf(v.y + b2s[kk + 1], 0.f);
        v.z = fmaxf(v.z + b2s[kk + 2], 0.f);
        v.w = fmaxf(v.w + b2s[kk + 3], 0.f);
        #pragma unroll
        for (int c = 0; c < 10; ++c) {
            acc[c] = fmaf(v.x, Wfs[(kk + 0) * 10 + c], acc[c]);
            acc[c] = fmaf(v.y, Wfs[(kk + 1) * 10 + c], acc[c]);
            acc[c] = fmaf(v.z, Wfs[(kk + 2) * 10 + c], acc[c]);
            acc[c] = fmaf(v.w, Wfs[(kk + 3) * 10 + c], acc[c]);
        }
    }

    float m = acc[0];
    #pragma unroll
    for (int c = 1; c < 10; ++c) m = fmaxf(m, acc[c]);
    float s = 0.f;
    float ex[10];
    #pragma unroll
    for (int c = 0; c < 10; ++c) { ex[c] = expf(acc[c] - m); s += ex[c]; }
    const float inv = 1.0f / s;
    #pragma unroll
    for (int c = 0; c < 10; ++c) out[(size_t)i * 10 + c] = ex[c] * inv;
}

// ---------------- launch ----------------
extern "C" void kernel_launch(void* const* d_in, const int* in_sizes, int n_in,
                              void* d_out, int out_size) {
    const float* x  = (const float*)d_in[0];
    const void*  ei = d_in[1];
    const float* W1 = (const float*)d_in[2];
    const float* b1 = (const float*)d_in[3];
    const float* W2 = (const float*)d_in[4];
    const float* b2 = (const float*)d_in[5];
    const float* Wf = (const float*)d_in[6];
    const float* bf = (const float*)d_in[7];
    float* out = (float*)d_out;

    const long long E = (long long)in_sizes[1] / 2;
    const int n = in_sizes[0] / D1;
    const int nb = (n + SCAN_BLK - 1) / SCAN_BLK;

    float *Hs1, *A1, *Hs2, *A2;
    cudaGetSymbolAddress((void**)&Hs1, g_Hs1);
    cudaGetSymbolAddress((void**)&A1, g_A1);
    cudaGetSymbolAddress((void**)&Hs2, g_Hs2);
    cudaGetSymbolAddress((void**)&A2, g_A2);

    cudaFuncSetAttribute(gemm_kernel<128, false>,
                         cudaFuncAttributeMaxDynamicSharedMemorySize, 81920);
    cudaFuncSetAttribute(gemm_kernel<64, true>,
                         cudaFuncAttributeMaxDynamicSharedMemorySize, 49152);

    // ---- CSR build ----
    detect_kernel<<<1, 256>>>((const unsigned int*)ei);
    zero_deg_kernel<<<(n + 255) / 256, 256>>>(n);
    if (E > 0) count_kernel<<<(int)((E + 255) / 256), 256>>>(ei, E);
    scanA_kernel<<<nb, SCAN_BLK>>>(n);
    scanB_kernel<<<1, MAXNB>>>(nb);
    scanC_kernel<<<nb, SCAN_BLK>>>(n);
    if (E > 0) fill_kernel<<<(int)((E + 255) / 256), 256>>>(ei, E);

    // ---- layer 1 ----
    gemm_kernel<128, false><<<(n + 127) / 128, 256, 81920>>>(x, W1, nullptr, Hs1, n);
    gather_kernel<128><<<(int)(((long long)n * 32 + 255) / 256), 256>>>(Hs1, A1, n);

    // ---- layer 2 (relu(+b1) fused into GEMM input load) ----
    gemm_kernel<64, true><<<(n + 127) / 128, 256, 49152>>>(A1, W2, b1, Hs2, n);
    gather_kernel<64><<<(int)(((long long)n * 16 + 255) / 256), 256>>>(Hs2, A2, n);

    // ---- final dense + softmax ----
    final_kernel<<<(n + 255) / 256, 256>>>(A2, b2, Wf, bf, out, n);
}